// round 5
// baseline (speedup 1.0000x reference)
#include <cuda_runtime.h>
#include <cstdint>

#define BB 4
#define CC 512
#define HH 56
#define NQ 3136
#define OQ 784
#define NH 8
#define HD 64
#define LEPS 1e-5f

static __device__ float g_xf[(size_t)BB*NQ*CC];
static __device__ float g_xs[(size_t)BB*OQ*CC];
static __device__ float g_qb[(size_t)BB*NQ*CC];
static __device__ float g_kb[(size_t)BB*OQ*CC];
static __device__ float g_vb[(size_t)BB*OQ*CC];
static __device__ float g_attn[(size_t)BB*NH*NQ*OQ];   // ~315 MB
static __device__ float g_ao[(size_t)BB*NQ*CC];
static __device__ float g_pssq[(size_t)BB*NH*NQ];
static __device__ float g_rstd[BB*NH];

// ---------------------------------------------------------------------------
// Transpose x (B,C,NQ) -> xf (B,NQ,C)
// ---------------------------------------------------------------------------
__global__ void k_transpose(const float* __restrict__ x) {
    __shared__ float t[32][33];
    int b = blockIdx.z;
    int q0 = blockIdx.x * 32, c0 = blockIdx.y * 32;
    int tx = threadIdx.x, ty = threadIdx.y;
#pragma unroll
    for (int i = 0; i < 32; i += 8)
        t[ty + i][tx] = x[((size_t)b * CC + c0 + ty + i) * NQ + q0 + tx];
    __syncthreads();
#pragma unroll
    for (int i = 0; i < 32; i += 8)
        g_xf[((size_t)b * NQ + q0 + ty + i) * CC + c0 + tx] = t[tx][ty + i];
}

// ---------------------------------------------------------------------------
// Depthwise 3x3 stride-2 pad-1 conv + bias -> g_xs (B,OQ,C)
// One block per (b,c); x-plane cached in shared.
// ---------------------------------------------------------------------------
__global__ void k_conv(const float* __restrict__ x, const float* __restrict__ w,
                       const float* __restrict__ bias) {
    int bc = blockIdx.x;
    int b = bc >> 9;
    int c = bc & 511;
    __shared__ float sx[HH * HH];
    const float* xp = x + ((size_t)b * CC + c) * NQ;
    for (int i = threadIdx.x; i < HH * HH; i += 256) sx[i] = xp[i];
    float w0 = w[c*9+0], w1 = w[c*9+1], w2 = w[c*9+2];
    float w3 = w[c*9+3], w4 = w[c*9+4], w5 = w[c*9+5];
    float w6 = w[c*9+6], w7 = w[c*9+7], w8 = w[c*9+8];
    float bi = bias[c];
    __syncthreads();
    for (int o = threadIdx.x; o < OQ; o += 256) {
        int oy = o / 28, ox = o - oy * 28;
        int y0 = oy * 2 - 1, x0 = ox * 2 - 1;
        float s = bi;
        if (y0 >= 0) {
            const float* r = &sx[y0 * HH];
            if (x0 >= 0) s += r[x0] * w0;
            s += r[x0 + 1] * w1 + r[x0 + 2] * w2;
        }
        {
            const float* r = &sx[(y0 + 1) * HH];
            if (x0 >= 0) s += r[x0] * w3;
            s += r[x0 + 1] * w4 + r[x0 + 2] * w5;
        }
        {
            const float* r = &sx[(y0 + 2) * HH];
            if (x0 >= 0) s += r[x0] * w6;
            s += r[x0 + 1] * w7 + r[x0 + 2] * w8;
        }
        g_xs[((size_t)b * OQ + o) * CC + c] = s;
    }
}

// ---------------------------------------------------------------------------
// LayerNorm over C=512 per (b,o), in place on g_xs
// ---------------------------------------------------------------------------
__global__ void k_ln(const float* __restrict__ gam, const float* __restrict__ bet) {
    int row = blockIdx.x;
    float* p = g_xs + (size_t)row * CC;
    int tid = threadIdx.x;
    float v0 = p[tid], v1 = p[tid + 256];
    float s = v0 + v1, sq = v0 * v0 + v1 * v1;
    __shared__ float r1[8], r2[8];
    __shared__ float s_m, s_r;
#pragma unroll
    for (int off = 16; off; off >>= 1) {
        s  += __shfl_xor_sync(0xffffffffu, s, off);
        sq += __shfl_xor_sync(0xffffffffu, sq, off);
    }
    if ((tid & 31) == 0) { r1[tid >> 5] = s; r2[tid >> 5] = sq; }
    __syncthreads();
    if (tid == 0) {
        float S = 0.f, Q = 0.f;
        for (int i = 0; i < 8; i++) { S += r1[i]; Q += r2[i]; }
        float mean = S * (1.f / CC);
        float var = Q * (1.f / CC) - mean * mean;
        s_m = mean;
        s_r = rsqrtf(var + LEPS);
    }
    __syncthreads();
    float mean = s_m, rs = s_r;
    p[tid]       = (v0 - mean) * rs * gam[tid]       + bet[tid];
    p[tid + 256] = (v1 - mean) * rs * gam[tid + 256] + bet[tid + 256];
}

// ---------------------------------------------------------------------------
// Generic tiled FP32 NT GEMM: C[m,n] = alpha * sum_k A[m,k]*W[n,k] (+bias)
// BM=128, BN=64, BK=16, 256 threads, 8x4 microtile.
// Batched via blockIdx.z: offsets = (z>>3)*s?b + (z&7)*s?h
// TRANS_OUT writes C[( (m/NQ)*N + n )*NQ + m%NQ]  (for final (B,C,HW) output)
// ---------------------------------------------------------------------------
template <bool TRANS_OUT, bool HAS_BIAS>
__global__ void __launch_bounds__(256)
k_gemm(const float* __restrict__ A, int lda, long long sAb, long long sAh,
       const float* __restrict__ W, int ldw, long long sWb, long long sWh,
       float* __restrict__ Cp, int ldc, long long sCb, long long sCh,
       int M, int N, int K, float alpha, const float* __restrict__ bias) {
    int bz = blockIdx.z;
    A  += (long long)(bz >> 3) * sAb + (long long)(bz & 7) * sAh;
    W  += (long long)(bz >> 3) * sWb + (long long)(bz & 7) * sWh;
    Cp += (long long)(bz >> 3) * sCb + (long long)(bz & 7) * sCh;
    int m0 = blockIdx.y * 128, n0 = blockIdx.x * 64;
    __shared__ float As[16][128];
    __shared__ float Bs[16][64];
    int tid = threadIdx.x;
    int tx = tid & 15, ty = tid >> 4;
    float acc[8][4] = {};
    int aR = tid >> 2, aK = (tid & 3) * 4;
    for (int k0 = 0; k0 < K; k0 += 16) {
#pragma unroll
        for (int it = 0; it < 2; it++) {
            int r = aR + it * 64, gm = m0 + r;
            float4 v = make_float4(0.f, 0.f, 0.f, 0.f);
            if (gm < M) v = *(const float4*)(A + (long long)gm * lda + k0 + aK);
            As[aK + 0][r] = v.x; As[aK + 1][r] = v.y;
            As[aK + 2][r] = v.z; As[aK + 3][r] = v.w;
        }
        {
            int gn = n0 + aR;
            float4 v = make_float4(0.f, 0.f, 0.f, 0.f);
            if (gn < N) v = *(const float4*)(W + (long long)gn * ldw + k0 + aK);
            Bs[aK + 0][aR] = v.x; Bs[aK + 1][aR] = v.y;
            Bs[aK + 2][aR] = v.z; Bs[aK + 3][aR] = v.w;
        }
        __syncthreads();
#pragma unroll
        for (int kk = 0; kk < 16; kk++) {
            float4 b4 = *(const float4*)&Bs[kk][tx * 4];
            float4 a0 = *(const float4*)&As[kk][ty * 8];
            float4 a1 = *(const float4*)&As[kk][ty * 8 + 4];
            float av[8] = {a0.x, a0.y, a0.z, a0.w, a1.x, a1.y, a1.z, a1.w};
            float bv[4] = {b4.x, b4.y, b4.z, b4.w};
#pragma unroll
            for (int i = 0; i < 8; i++)
#pragma unroll
                for (int j = 0; j < 4; j++)
                    acc[i][j] += av[i] * bv[j];
        }
        __syncthreads();
    }
#pragma unroll
    for (int i = 0; i < 8; i++) {
        int m = m0 + ty * 8 + i;
        if (m >= M) continue;
#pragma unroll
        for (int j = 0; j < 4; j++) {
            int n = n0 + tx * 4 + j;
            if (n >= N) continue;
            float vv = acc[i][j] * alpha;
            if (HAS_BIAS) vv += bias[n];
            if (TRANS_OUT) {
                int bidx = m / NQ, q = m - bidx * NQ;
                Cp[((long long)bidx * N + n) * NQ + q] = vv;
            } else {
                Cp[(long long)m * ldc + n] = vv;
            }
        }
    }
}

// ---------------------------------------------------------------------------
// Fused head-mix (tc_w/tc_b) + softmax over OQ, in place on g_attn.
// One block per (b,q) row. Emits per-row sum-of-squares partials (deterministic).
// InstanceNorm mean is exactly 1/OQ (softmax rows sum to 1).
// ---------------------------------------------------------------------------
__global__ void __launch_bounds__(256)
k_mixsoftmax(const float* __restrict__ tcw, const float* __restrict__ tcb) {
    int bq = blockIdx.x;
    int b = bq / NQ;
    int q = bq - b * NQ;
    int tid = threadIdx.x;
    __shared__ float s_w[64];
    __shared__ float s_b[8];
    __shared__ float sred[8];
    __shared__ float s_bc;
    if (tid < 64) s_w[tid] = tcw[tid];
    if (tid < 8)  s_b[tid] = tcb[tid];
    __syncthreads();
    const long long HS = (long long)NQ * OQ;
    long long base0 = (long long)b * NH * HS + (long long)q * OQ;
    float m[8][4];
#pragma unroll
    for (int j = 0; j < 4; j++) {
        int o = tid + j * 256;
        bool valid = o < OQ;
        float lh[8];
#pragma unroll
        for (int h = 0; h < 8; h++)
            lh[h] = valid ? g_attn[base0 + (long long)h * HS + o] : 0.f;
#pragma unroll
        for (int g2 = 0; g2 < 8; g2++) {
            float s = s_b[g2];
#pragma unroll
            for (int h = 0; h < 8; h++) s += s_w[g2 * 8 + h] * lh[h];
            m[g2][j] = valid ? s : -1e30f;
        }
    }
    for (int g2 = 0; g2 < 8; g2++) {
        float lm = fmaxf(fmaxf(m[g2][0], m[g2][1]), fmaxf(m[g2][2], m[g2][3]));
#pragma unroll
        for (int off = 16; off; off >>= 1)
            lm = fmaxf(lm, __shfl_xor_sync(0xffffffffu, lm, off));
        if ((tid & 31) == 0) sred[tid >> 5] = lm;
        __syncthreads();
        if (tid == 0) {
            float v = sred[0];
            for (int i = 1; i < 8; i++) v = fmaxf(v, sred[i]);
            s_bc = v;
        }
        __syncthreads();
        float gmax = s_bc;
        float e[4];
        float ls = 0.f;
#pragma unroll
        for (int j = 0; j < 4; j++) { e[j] = __expf(m[g2][j] - gmax); ls += e[j]; }
#pragma unroll
        for (int off = 16; off; off >>= 1)
            ls += __shfl_xor_sync(0xffffffffu, ls, off);
        if ((tid & 31) == 0) sred[tid >> 5] = ls;
        __syncthreads();
        if (tid == 0) {
            float v = 0.f;
            for (int i = 0; i < 8; i++) v += sred[i];
            s_bc = v;
        }
        __syncthreads();
        float inv = 1.f / s_bc;
        float ssq = 0.f;
#pragma unroll
        for (int j = 0; j < 4; j++) {
            int o = tid + j * 256;
            if (o < OQ) {
                float a = e[j] * inv;
                g_attn[base0 + (long long)g2 * HS + o] = a;
                ssq += a * a;
            }
        }
#pragma unroll
        for (int off = 16; off; off >>= 1)
            ssq += __shfl_xor_sync(0xffffffffu, ssq, off);
        if ((tid & 31) == 0) sred[tid >> 5] = ssq;
        __syncthreads();
        if (tid == 0) {
            float v = 0.f;
            for (int i = 0; i < 8; i++) v += sred[i];
            g_pssq[(long long)(b * NH + g2) * NQ + q] = v;
        }
        __syncthreads();
    }
}

// ---------------------------------------------------------------------------
// Finalize instance-norm rstd per (b,h)
// ---------------------------------------------------------------------------
__global__ void k_rstd() {
    int z = blockIdx.x;
    int tid = threadIdx.x;
    float s = 0.f;
    for (int i = tid; i < NQ; i += 256) s += g_pssq[(long long)z * NQ + i];
    __shared__ float r1[8];
#pragma unroll
    for (int off = 16; off; off >>= 1)
        s += __shfl_xor_sync(0xffffffffu, s, off);
    if ((tid & 31) == 0) r1[tid >> 5] = s;
    __syncthreads();
    if (tid == 0) {
        float S = 0.f;
        for (int i = 0; i < 8; i++) S += r1[i];
        const float mean = 1.f / OQ;
        float var = S / ((float)NQ * (float)OQ) - mean * mean;
        g_rstd[z] = rsqrtf(var + LEPS);
    }
}

// ---------------------------------------------------------------------------
// AV GEMM per (b,h): out[q,d] = sum_o ((a-mean)*rstd*w)[q,o] * v[o,d]
// A fused on the fly. M=3136 (BM=128), N=64, K=784 (BK=16).
// ---------------------------------------------------------------------------
__global__ void __launch_bounds__(256) k_attnv(const float* __restrict__ wgt) {
    int z = blockIdx.y;
    int b = z >> 3, h = z & 7;
    int m0 = blockIdx.x * 128;
    const long long base = (long long)z * NQ * OQ;
    float rs = g_rstd[z];
    const float mean = 1.f / OQ;
    __shared__ float As[16][128];
    __shared__ float Bs[16][64];
    int tid = threadIdx.x;
    int tx = tid & 15, ty = tid >> 4;
    float acc[8][4] = {};
    int aR = tid >> 2, aK = (tid & 3) * 4;
    int vD = (tid & 15) * 4, vK = tid >> 4;
    for (int k0 = 0; k0 < OQ; k0 += 16) {
#pragma unroll
        for (int it = 0; it < 2; it++) {
            int r = aR + it * 64, gm = m0 + r;
            float4 av = make_float4(0.f, 0.f, 0.f, 0.f);
            float4 wv = av;
            if (gm < NQ) {
                long long idx = base + (long long)gm * OQ + k0 + aK;
                av = *(const float4*)(g_attn + idx);
                wv = *(const float4*)(wgt + idx);
            }
            As[aK + 0][r] = (av.x - mean) * rs * wv.x;
            As[aK + 1][r] = (av.y - mean) * rs * wv.y;
            As[aK + 2][r] = (av.z - mean) * rs * wv.z;
            As[aK + 3][r] = (av.w - mean) * rs * wv.w;
        }
        {
            float4 vv = *(const float4*)(g_vb + ((long long)b * OQ + k0 + vK) * CC + h * HD + vD);
            *(float4*)&Bs[vK][vD] = vv;
        }
        __syncthreads();
#pragma unroll
        for (int kk = 0; kk < 16; kk++) {
            float4 b4 = *(const float4*)&Bs[kk][tx * 4];
            float4 a0 = *(const float4*)&As[kk][ty * 8];
            float4 a1 = *(const float4*)&As[kk][ty * 8 + 4];
            float av2[8] = {a0.x, a0.y, a0.z, a0.w, a1.x, a1.y, a1.z, a1.w};
            float bv2[4] = {b4.x, b4.y, b4.z, b4.w};
#pragma unroll
            for (int i = 0; i < 8; i++)
#pragma unroll
                for (int j = 0; j < 4; j++)
                    acc[i][j] += av2[i] * bv2[j];
        }
        __syncthreads();
    }
#pragma unroll
    for (int i = 0; i < 8; i++) {
        int m = m0 + ty * 8 + i;
        if (m >= NQ) continue;
#pragma unroll
        for (int j = 0; j < 4; j++) {
            int n = tx * 4 + j;
            g_ao[((long long)b * NQ + m) * CC + h * HD + n] = acc[i][j];
        }
    }
}

// ---------------------------------------------------------------------------
extern "C" void kernel_launch(void* const* d_in, const int* in_sizes, int n_in,
                              void* d_out, int out_size) {
    const float* x    = (const float*)d_in[0];
    const float* aw   = (const float*)d_in[1];
    const float* q_w  = (const float*)d_in[2];
    const float* k_w  = (const float*)d_in[3];
    const float* v_w  = (const float*)d_in[4];
    const float* sr_w = (const float*)d_in[5];
    const float* sr_b = (const float*)d_in[6];
    const float* ln_g = (const float*)d_in[7];
    const float* ln_b = (const float*)d_in[8];
    const float* tc_w = (const float*)d_in[9];
    const float* tc_b = (const float*)d_in[10];
    const float* pj_w = (const float*)d_in[11];
    const float* pj_b = (const float*)d_in[12];
    float* out = (float*)d_out;

    static bool s_init = false;
    static float *p_xf, *p_xs, *p_q, *p_k, *p_v, *p_attn, *p_ao;
    if (!s_init) {
        cudaGetSymbolAddress((void**)&p_xf, g_xf);
        cudaGetSymbolAddress((void**)&p_xs, g_xs);
        cudaGetSymbolAddress((void**)&p_q, g_qb);
        cudaGetSymbolAddress((void**)&p_k, g_kb);
        cudaGetSymbolAddress((void**)&p_v, g_vb);
        cudaGetSymbolAddress((void**)&p_attn, g_attn);
        cudaGetSymbolAddress((void**)&p_ao, g_ao);
        s_init = true;
    }

    // Stage A: layouts + spatial reduction
    k_transpose<<<dim3(98, 16, 4), dim3(32, 8)>>>(x);
    k_conv<<<BB * CC, 256>>>(x, sr_w, sr_b);
    k_ln<<<BB * OQ, 256>>>(ln_g, ln_b);

    // Stage B: projections
    k_gemm<false, false><<<dim3(8, 98, 1), 256>>>(
        p_xf, CC, 0, 0, q_w, CC, 0, 0, p_q, CC, 0, 0,
        BB * NQ, CC, CC, 1.f, nullptr);
    k_gemm<false, false><<<dim3(8, 25, 1), 256>>>(
        p_xs, CC, 0, 0, k_w, CC, 0, 0, p_k, CC, 0, 0,
        BB * OQ, CC, CC, 1.f, nullptr);
    k_gemm<false, false><<<dim3(8, 25, 1), 256>>>(
        p_xs, CC, 0, 0, v_w, CC, 0, 0, p_v, CC, 0, 0,
        BB * OQ, CC, CC, 1.f, nullptr);

    // Stage C: per-head QK logits (batched over 32 = B*NH), scaled by hd^-0.5
    k_gemm<false, false><<<dim3(13, 25, 32), 256>>>(
        p_q, CC, (long long)NQ * CC, HD,
        p_k, CC, (long long)OQ * CC, HD,
        p_attn, OQ, (long long)NH * NQ * OQ, (long long)NQ * OQ,
        NQ, OQ, HD, 0.125f, nullptr);

    // head-mix + softmax + instnorm stats
    k_mixsoftmax<<<BB * NQ, 256>>>(tc_w, tc_b);
    k_rstd<<<32, 256>>>();

    // Stage D: (instnorm * attn_weights) @ V
    k_attnv<<<dim3(25, 32), 256>>>(aw);

    // Stage E: output projection + bias, written transposed into (B,C,HW)
    k_gemm<true, true><<<dim3(8, 98, 1), 256>>>(
        p_ao, CC, 0, 0, pj_w, CC, 0, 0, out, CC, 0, 0,
        BB * NQ, CC, CC, 1.f, pj_b);
}

// round 6
// speedup vs baseline: 1.3640x; 1.3640x over previous
#include <cuda_runtime.h>
#include <cstdint>

#define BB 4
#define CC 512
#define HH 56
#define NQ 3136
#define OQ 784
#define NH 8
#define HD 64
#define LEPS 1e-5f

#define BM 128
#define BN 64
#define BK 16

static __device__ float g_xf[(size_t)BB*NQ*CC];
static __device__ float g_xs[(size_t)BB*OQ*CC];
static __device__ float g_qb[(size_t)BB*NQ*CC];
static __device__ float g_kb[(size_t)BB*OQ*CC];
static __device__ float g_vt[(size_t)BB*CC*OQ];    // V transposed: (B, C, OQ)
static __device__ float g_attn[(size_t)BB*NH*NQ*OQ];   // ~315 MB
static __device__ float g_ao[(size_t)BB*NQ*CC];
static __device__ float g_pssq[(size_t)BB*NH*NQ];
static __device__ float g_rstd[BB*NH];

// ---------------------------------------------------------------------------
// Transpose x (B,C,NQ) -> xf (B,NQ,C)
// ---------------------------------------------------------------------------
__global__ void k_transpose(const float* __restrict__ x) {
    __shared__ float t[32][33];
    int b = blockIdx.z;
    int q0 = blockIdx.x * 32, c0 = blockIdx.y * 32;
    int tx = threadIdx.x, ty = threadIdx.y;
#pragma unroll
    for (int i = 0; i < 32; i += 8)
        t[ty + i][tx] = x[((size_t)b * CC + c0 + ty + i) * NQ + q0 + tx];
    __syncthreads();
#pragma unroll
    for (int i = 0; i < 32; i += 8)
        g_xf[((size_t)b * NQ + q0 + ty + i) * CC + c0 + tx] = t[tx][ty + i];
}

// ---------------------------------------------------------------------------
// Depthwise 3x3 stride-2 pad-1 conv + bias -> g_xs (B,OQ,C)
// ---------------------------------------------------------------------------
__global__ void k_conv(const float* __restrict__ x, const float* __restrict__ w,
                       const float* __restrict__ bias) {
    int bc = blockIdx.x;
    int b = bc >> 9;
    int c = bc & 511;
    __shared__ float sx[HH * HH];
    const float* xp = x + ((size_t)b * CC + c) * NQ;
    for (int i = threadIdx.x; i < HH * HH; i += 256) sx[i] = xp[i];
    float w0 = w[c*9+0], w1 = w[c*9+1], w2 = w[c*9+2];
    float w3 = w[c*9+3], w4 = w[c*9+4], w5 = w[c*9+5];
    float w6 = w[c*9+6], w7 = w[c*9+7], w8 = w[c*9+8];
    float bi = bias[c];
    __syncthreads();
    for (int o = threadIdx.x; o < OQ; o += 256) {
        int oy = o / 28, ox = o - oy * 28;
        int y0 = oy * 2 - 1, x0 = ox * 2 - 1;
        float s = bi;
        if (y0 >= 0) {
            const float* r = &sx[y0 * HH];
            if (x0 >= 0) s += r[x0] * w0;
            s += r[x0 + 1] * w1 + r[x0 + 2] * w2;
        }
        {
            const float* r = &sx[(y0 + 1) * HH];
            if (x0 >= 0) s += r[x0] * w3;
            s += r[x0 + 1] * w4 + r[x0 + 2] * w5;
        }
        {
            const float* r = &sx[(y0 + 2) * HH];
            if (x0 >= 0) s += r[x0] * w6;
            s += r[x0 + 1] * w7 + r[x0 + 2] * w8;
        }
        g_xs[((size_t)b * OQ + o) * CC + c] = s;
    }
}

// ---------------------------------------------------------------------------
// LayerNorm over C=512 per (b,o), in place on g_xs
// ---------------------------------------------------------------------------
__global__ void k_ln(const float* __restrict__ gam, const float* __restrict__ bet) {
    int row = blockIdx.x;
    float* p = g_xs + (size_t)row * CC;
    int tid = threadIdx.x;
    float v0 = p[tid], v1 = p[tid + 256];
    float s = v0 + v1, sq = v0 * v0 + v1 * v1;
    __shared__ float r1[8], r2[8];
    __shared__ float s_m, s_r;
#pragma unroll
    for (int off = 16; off; off >>= 1) {
        s  += __shfl_xor_sync(0xffffffffu, s, off);
        sq += __shfl_xor_sync(0xffffffffu, sq, off);
    }
    if ((tid & 31) == 0) { r1[tid >> 5] = s; r2[tid >> 5] = sq; }
    __syncthreads();
    if (tid == 0) {
        float S = 0.f, Q = 0.f;
        for (int i = 0; i < 8; i++) { S += r1[i]; Q += r2[i]; }
        float mean = S * (1.f / CC);
        float var = Q * (1.f / CC) - mean * mean;
        s_m = mean;
        s_r = rsqrtf(var + LEPS);
    }
    __syncthreads();
    float mean = s_m, rs = s_r;
    p[tid]       = (v0 - mean) * rs * gam[tid]       + bet[tid];
    p[tid + 256] = (v1 - mean) * rs * gam[tid + 256] + bet[tid + 256];
}

// ---------------------------------------------------------------------------
// tf32 round
// ---------------------------------------------------------------------------
__device__ __forceinline__ float tf32r(float x) {
    uint32_t u;
    asm("cvt.rna.tf32.f32 %0, %1;" : "=r"(u) : "f"(x));
    return __uint_as_float(u);
}

// ---------------------------------------------------------------------------
// TF32 tensor-core NT GEMM: C[m,n] = alpha * sum_k A[m,k]*W[n,k] (+bias)
// BM=128, BN=64, BK=16; 256 threads = 8 warps (4 along M x 2 along N);
// warptile 32x32 = 2x4 tiles of mma.m16n8k8. Double-buffered smem with XOR
// swizzle (float4 idx = k4*DIM + (row ^ (k4<<1))) -> conflict-free STS.128
// stores and LDS.32 fragment loads.
// Batched over blockIdx.z: offset = (z>>3)*s?b + (z&7)*s?h.
// TRANS_OUT: write Cp[((m/trows)*N + n)*trows + m%trows].
// FUSE_A: A-elem -> (a - 1/OQ) * rstd[z] * A2-elem.
// ---------------------------------------------------------------------------
template <bool TRANS_OUT, bool HAS_BIAS, bool FUSE_A>
__global__ void __launch_bounds__(256)
k_mma(const float* __restrict__ A, int lda, long long sAb, long long sAh,
      const float* __restrict__ W, int ldw, long long sWb, long long sWh,
      float* __restrict__ Cp, int ldc, long long sCb, long long sCh,
      int M, int N, int K, float alpha, const float* __restrict__ bias,
      int trows, const float* __restrict__ A2, const float* __restrict__ rstdp) {
    __shared__ float4 As4[2][4 * BM];
    __shared__ float4 Bs4[2][4 * BN];

    int bz = blockIdx.z;
    long long offA = (long long)(bz >> 3) * sAb + (long long)(bz & 7) * sAh;
    A += offA;
    W += (long long)(bz >> 3) * sWb + (long long)(bz & 7) * sWh;
    Cp += (long long)(bz >> 3) * sCb + (long long)(bz & 7) * sCh;
    float rs = 0.f;
    const float amean = 1.f / OQ;
    if (FUSE_A) { A2 += offA; rs = rstdp[bz]; }

    int m0 = blockIdx.y * BM, n0 = blockIdx.x * BN;
    int tid = threadIdx.x;
    int lane = tid & 31, warp = tid >> 5;
    int wm = (warp & 3) * 32, wn = (warp >> 2) * 32;
    int gid = lane >> 2, tig = lane & 3;

    int lk4 = tid & 3;        // loader k4 (0..3)
    int lrow = tid >> 2;      // loader row  (0..63)

    float4 ra[2], rb;
    float acc[2][4][4];
#pragma unroll
    for (int i = 0; i < 2; i++)
#pragma unroll
        for (int j = 0; j < 4; j++)
#pragma unroll
            for (int l = 0; l < 4; l++) acc[i][j][l] = 0.f;

#define LOAD_TILE(K0)                                                          \
    {                                                                          \
        _Pragma("unroll")                                                      \
        for (int it = 0; it < 2; it++) {                                       \
            int m = lrow + it * 64;                                            \
            int gm = m0 + m;                                                   \
            float4 v = make_float4(0.f, 0.f, 0.f, 0.f);                        \
            if (gm < M) {                                                      \
                v = *(const float4*)(A + (size_t)gm * lda + (K0) + lk4 * 4);   \
                if (FUSE_A) {                                                  \
                    float4 w2 = *(const float4*)(A2 + (size_t)gm * lda + (K0) + lk4 * 4); \
                    v.x = (v.x - amean) * rs * w2.x;                           \
                    v.y = (v.y - amean) * rs * w2.y;                           \
                    v.z = (v.z - amean) * rs * w2.z;                           \
                    v.w = (v.w - amean) * rs * w2.w;                           \
                }                                                              \
            }                                                                  \
            ra[it] = v;                                                        \
        }                                                                      \
        {                                                                      \
            int gn = n0 + lrow;                                                \
            float4 v = make_float4(0.f, 0.f, 0.f, 0.f);                        \
            if (gn < N)                                                        \
                v = *(const float4*)(W + (size_t)gn * ldw + (K0) + lk4 * 4);   \
            rb = v;                                                            \
        }                                                                      \
    }

#define STORE_TILE(BUF)                                                        \
    {                                                                          \
        _Pragma("unroll")                                                      \
        for (int it = 0; it < 2; it++) {                                       \
            int m = lrow + it * 64;                                            \
            float4 v = ra[it];                                                 \
            v.x = tf32r(v.x); v.y = tf32r(v.y);                                \
            v.z = tf32r(v.z); v.w = tf32r(v.w);                                \
            As4[BUF][lk4 * BM + (m ^ (lk4 << 1))] = v;                         \
        }                                                                      \
        {                                                                      \
            float4 v = rb;                                                     \
            v.x = tf32r(v.x); v.y = tf32r(v.y);                                \
            v.z = tf32r(v.z); v.w = tf32r(v.w);                                \
            Bs4[BUF][lk4 * BN + (lrow ^ (lk4 << 1))] = v;                      \
        }                                                                      \
    }

#define COMPUTE(BUF)                                                           \
    {                                                                          \
        const float* Af = (const float*)As4[BUF];                              \
        const float* Bf = (const float*)Bs4[BUF];                              \
        _Pragma("unroll")                                                      \
        for (int ks = 0; ks < 2; ks++) {                                       \
            int k4a = ks * 2, k4b = ks * 2 + 1;                                \
            uint32_t af[2][4], bf[4][2];                                       \
            _Pragma("unroll")                                                  \
            for (int mi = 0; mi < 2; mi++) {                                   \
                int ma = wm + mi * 16 + gid;                                   \
                af[mi][0] = __float_as_uint(Af[(k4a * BM + (ma ^ (k4a << 1))) * 4 + tig]);        \
                af[mi][1] = __float_as_uint(Af[(k4a * BM + ((ma + 8) ^ (k4a << 1))) * 4 + tig]);  \
                af[mi][2] = __float_as_uint(Af[(k4b * BM + (ma ^ (k4b << 1))) * 4 + tig]);        \
                af[mi][3] = __float_as_uint(Af[(k4b * BM + ((ma + 8) ^ (k4b << 1))) * 4 + tig]);  \
            }                                                                  \
            _Pragma("unroll")                                                  \
            for (int ni = 0; ni < 4; ni++) {                                   \
                int nb = wn + ni * 8 + gid;                                    \
                bf[ni][0] = __float_as_uint(Bf[(k4a * BN + (nb ^ (k4a << 1))) * 4 + tig]);        \
                bf[ni][1] = __float_as_uint(Bf[(k4b * BN + (nb ^ (k4b << 1))) * 4 + tig]);        \
            }                                                                  \
            _Pragma("unroll")                                                  \
            for (int mi = 0; mi < 2; mi++)                                     \
            _Pragma("unroll")                                                  \
            for (int ni = 0; ni < 4; ni++) {                                   \
                asm volatile(                                                  \
                    "mma.sync.aligned.m16n8k8.row.col.f32.tf32.tf32.f32 "      \
                    "{%0,%1,%2,%3}, {%4,%5,%6,%7}, {%8,%9}, {%0,%1,%2,%3};"    \
                    : "+f"(acc[mi][ni][0]), "+f"(acc[mi][ni][1]),              \
                      "+f"(acc[mi][ni][2]), "+f"(acc[mi][ni][3])               \
                    : "r"(af[mi][0]), "r"(af[mi][1]),                          \
                      "r"(af[mi][2]), "r"(af[mi][3]),                          \
                      "r"(bf[ni][0]), "r"(bf[ni][1]));                         \
            }                                                                  \
        }                                                                      \
    }

    LOAD_TILE(0);
    STORE_TILE(0);
    __syncthreads();
    int nkb = K / BK;
    for (int kb = 0; kb < nkb; kb++) {
        int buf = kb & 1;
        if (kb + 1 < nkb) LOAD_TILE((kb + 1) * BK);
        COMPUTE(buf);
        if (kb + 1 < nkb) {
            STORE_TILE(buf ^ 1);
            __syncthreads();
        }
    }

    // epilogue
#pragma unroll
    for (int mi = 0; mi < 2; mi++)
#pragma unroll
    for (int ni = 0; ni < 4; ni++) {
        int r0 = m0 + wm + mi * 16 + gid;
        int c0 = n0 + wn + ni * 8 + tig * 2;
#pragma unroll
        for (int half = 0; half < 2; half++) {
            int r = r0 + half * 8;
            if (r >= M) continue;
#pragma unroll
            for (int cc2 = 0; cc2 < 2; cc2++) {
                int c = c0 + cc2;
                if (c >= N) continue;
                float vv = acc[mi][ni][half * 2 + cc2] * alpha;
                if (HAS_BIAS) vv += bias[c];
                if (TRANS_OUT) {
                    int bidx = r / trows, q = r - bidx * trows;
                    Cp[((long long)bidx * N + c) * trows + q] = vv;
                } else {
                    Cp[(long long)r * ldc + c] = vv;
                }
            }
        }
    }
#undef LOAD_TILE
#undef STORE_TILE
#undef COMPUTE
}

// ---------------------------------------------------------------------------
// Fused head-mix (tc_w/tc_b) + softmax over OQ, in place on g_attn.
// ---------------------------------------------------------------------------
__global__ void __launch_bounds__(256)
k_mixsoftmax(const float* __restrict__ tcw, const float* __restrict__ tcb) {
    int bq = blockIdx.x;
    int b = bq / NQ;
    int q = bq - b * NQ;
    int tid = threadIdx.x;
    __shared__ float s_w[64];
    __shared__ float s_b[8];
    __shared__ float sred[8];
    __shared__ float s_bc;
    if (tid < 64) s_w[tid] = tcw[tid];
    if (tid < 8)  s_b[tid] = tcb[tid];
    __syncthreads();
    const long long HS = (long long)NQ * OQ;
    long long base0 = (long long)b * NH * HS + (long long)q * OQ;
    float m[8][4];
#pragma unroll
    for (int j = 0; j < 4; j++) {
        int o = tid + j * 256;
        bool valid = o < OQ;
        float lh[8];
#pragma unroll
        for (int h = 0; h < 8; h++)
            lh[h] = valid ? g_attn[base0 + (long long)h * HS + o] : 0.f;
#pragma unroll
        for (int g2 = 0; g2 < 8; g2++) {
            float s = s_b[g2];
#pragma unroll
            for (int h = 0; h < 8; h++) s += s_w[g2 * 8 + h] * lh[h];
            m[g2][j] = valid ? s : -1e30f;
        }
    }
    for (int g2 = 0; g2 < 8; g2++) {
        float lm = fmaxf(fmaxf(m[g2][0], m[g2][1]), fmaxf(m[g2][2], m[g2][3]));
#pragma unroll
        for (int off = 16; off; off >>= 1)
            lm = fmaxf(lm, __shfl_xor_sync(0xffffffffu, lm, off));
        if ((tid & 31) == 0) sred[tid >> 5] = lm;
        __syncthreads();
        if (tid == 0) {
            float v = sred[0];
            for (int i = 1; i < 8; i++) v = fmaxf(v, sred[i]);
            s_bc = v;
        }
        __syncthreads();
        float gmax = s_bc;
        float e[4];
        float ls = 0.f;
#pragma unroll
        for (int j = 0; j < 4; j++) { e[j] = __expf(m[g2][j] - gmax); ls += e[j]; }
#pragma unroll
        for (int off = 16; off; off >>= 1)
            ls += __shfl_xor_sync(0xffffffffu, ls, off);
        if ((tid & 31) == 0) sred[tid >> 5] = ls;
        __syncthreads();
        if (tid == 0) {
            float v = 0.f;
            for (int i = 0; i < 8; i++) v += sred[i];
            s_bc = v;
        }
        __syncthreads();
        float inv = 1.f / s_bc;
        float ssq = 0.f;
#pragma unroll
        for (int j = 0; j < 4; j++) {
            int o = tid + j * 256;
            if (o < OQ) {
                float a = e[j] * inv;
                g_attn[base0 + (long long)g2 * HS + o] = a;
                ssq += a * a;
            }
        }
#pragma unroll
        for (int off = 16; off; off >>= 1)
            ssq += __shfl_xor_sync(0xffffffffu, ssq, off);
        if ((tid & 31) == 0) sred[tid >> 5] = ssq;
        __syncthreads();
        if (tid == 0) {
            float v = 0.f;
            for (int i = 0; i < 8; i++) v += sred[i];
            g_pssq[(long long)(b * NH + g2) * NQ + q] = v;
        }
        __syncthreads();
    }
}

// ---------------------------------------------------------------------------
// Finalize instance-norm rstd per (b,h)
// ---------------------------------------------------------------------------
__global__ void k_rstd() {
    int z = blockIdx.x;
    int tid = threadIdx.x;
    float s = 0.f;
    for (int i = tid; i < NQ; i += 256) s += g_pssq[(long long)z * NQ + i];
    __shared__ float r1[8];
#pragma unroll
    for (int off = 16; off; off >>= 1)
        s += __shfl_xor_sync(0xffffffffu, s, off);
    if ((tid & 31) == 0) r1[tid >> 5] = s;
    __syncthreads();
    if (tid == 0) {
        float S = 0.f;
        for (int i = 0; i < 8; i++) S += r1[i];
        const float mean = 1.f / OQ;
        float var = S / ((float)NQ * (float)OQ) - mean * mean;
        g_rstd[z] = rsqrtf(var + LEPS);
    }
}

// ---------------------------------------------------------------------------
extern "C" void kernel_launch(void* const* d_in, const int* in_sizes, int n_in,
                              void* d_out, int out_size) {
    const float* x    = (const float*)d_in[0];
    const float* aw   = (const float*)d_in[1];
    const float* q_w  = (const float*)d_in[2];
    const float* k_w  = (const float*)d_in[3];
    const float* v_w  = (const float*)d_in[4];
    const float* sr_w = (const float*)d_in[5];
    const float* sr_b = (const float*)d_in[6];
    const float* ln_g = (const float*)d_in[7];
    const float* ln_b = (const float*)d_in[8];
    const float* tc_w = (const float*)d_in[9];
    const float* tc_b = (const float*)d_in[10];
    const float* pj_w = (const float*)d_in[11];
    const float* pj_b = (const float*)d_in[12];
    float* out = (float*)d_out;

    static bool s_init = false;
    static float *p_xf, *p_xs, *p_q, *p_k, *p_vt, *p_attn, *p_ao, *p_rstd;
    if (!s_init) {
        cudaGetSymbolAddress((void**)&p_xf, g_xf);
        cudaGetSymbolAddress((void**)&p_xs, g_xs);
        cudaGetSymbolAddress((void**)&p_q, g_qb);
        cudaGetSymbolAddress((void**)&p_k, g_kb);
        cudaGetSymbolAddress((void**)&p_vt, g_vt);
        cudaGetSymbolAddress((void**)&p_attn, g_attn);
        cudaGetSymbolAddress((void**)&p_ao, g_ao);
        cudaGetSymbolAddress((void**)&p_rstd, g_rstd);
        s_init = true;
    }

    // Stage A: layouts + spatial reduction
    k_transpose<<<dim3(98, 16, 4), dim3(32, 8)>>>(x);
    k_conv<<<BB * CC, 256>>>(x, sr_w, sr_b);
    k_ln<<<BB * OQ, 256>>>(ln_g, ln_b);

    // Stage B: projections (tf32 tensor cores)
    // Q: (B*NQ, 512) = xf @ q_w^T
    k_mma<false, false, false><<<dim3(8, 98, 1), 256>>>(
        p_xf, CC, 0, 0, q_w, CC, 0, 0, p_q, CC, 0, 0,
        BB * NQ, CC, CC, 1.f, nullptr, 0, nullptr, nullptr);
    // K: (B*OQ, 512) = xs @ k_w^T
    k_mma<false, false, false><<<dim3(8, 25, 1), 256>>>(
        p_xs, CC, 0, 0, k_w, CC, 0, 0, p_k, CC, 0, 0,
        BB * OQ, CC, CC, 1.f, nullptr, 0, nullptr, nullptr);
    // V: transposed write -> g_vt (B, C, OQ)
    k_mma<true, false, false><<<dim3(8, 25, 1), 256>>>(
        p_xs, CC, 0, 0, v_w, CC, 0, 0, p_vt, 0, 0, 0,
        BB * OQ, CC, CC, 1.f, nullptr, OQ, nullptr, nullptr);

    // Stage C: per-head QK logits (batched over 32 = B*NH), scaled by hd^-0.5
    k_mma<false, false, false><<<dim3(13, 25, 32), 256>>>(
        p_q, CC, (long long)NQ * CC, HD,
        p_k, CC, (long long)OQ * CC, HD,
        p_attn, OQ, (long long)NH * NQ * OQ, (long long)NQ * OQ,
        NQ, OQ, HD, 0.125f, nullptr, 0, nullptr, nullptr);

    // head-mix + softmax + instnorm stats
    k_mixsoftmax<<<BB * NQ, 256>>>(tc_w, tc_b);
    k_rstd<<<32, 256>>>();

    // Stage D: fused (instnorm * attn_weights) @ V  (V from g_vt, K-contig)
    k_mma<false, false, true><<<dim3(1, 25, 32), 256>>>(
        p_attn, OQ, (long long)NH * NQ * OQ, (long long)NQ * OQ,
        p_vt, OQ, (long long)CC * OQ, (long long)HD * OQ,
        p_ao, CC, (long long)NQ * CC, HD,
        NQ, HD, OQ, 1.f, nullptr, 0, aw, p_rstd);

    // Stage E: output projection + bias, written transposed into (B,C,HW)
    k_mma<true, true, false><<<dim3(8, 98, 1), 256>>>(
        p_ao, CC, 0, 0, pj_w, CC, 0, 0, out, 0, 0, 0,
        BB * NQ, CC, CC, 1.f, pj_b, NQ, nullptr, nullptr);
}

// round 7
// speedup vs baseline: 1.9187x; 1.4067x over previous
#include <cuda_runtime.h>
#include <cstdint>

#define BB 4
#define CC 512
#define HH 56
#define NQ 3136
#define OQ 784
#define NH 8
#define HD 64
#define LEPS 1e-5f

#define BM 128
#define BN 64
#define BK 16

static __device__ float g_xf[(size_t)BB*NQ*CC];
static __device__ float g_xs[(size_t)BB*OQ*CC];
static __device__ float g_qb[(size_t)BB*NQ*CC];
static __device__ float g_kb[(size_t)BB*OQ*CC];
static __device__ float g_vt[(size_t)BB*CC*OQ];    // V transposed: (B, C, OQ)
static __device__ float g_attn[(size_t)BB*NH*NQ*OQ];   // ~315 MB
static __device__ float g_ao[(size_t)BB*NQ*CC];
static __device__ float g_pssq[(size_t)BB*NH*NQ];
static __device__ float g_rstd[BB*NH];

// ---------------------------------------------------------------------------
// Transpose x (B,C,NQ) -> xf (B,NQ,C)
// ---------------------------------------------------------------------------
__global__ void k_transpose(const float* __restrict__ x) {
    __shared__ float t[32][33];
    int b = blockIdx.z;
    int q0 = blockIdx.x * 32, c0 = blockIdx.y * 32;
    int tx = threadIdx.x, ty = threadIdx.y;
#pragma unroll
    for (int i = 0; i < 32; i += 8)
        t[ty + i][tx] = x[((size_t)b * CC + c0 + ty + i) * NQ + q0 + tx];
    __syncthreads();
#pragma unroll
    for (int i = 0; i < 32; i += 8)
        g_xf[((size_t)b * NQ + q0 + ty + i) * CC + c0 + tx] = t[tx][ty + i];
}

// ---------------------------------------------------------------------------
// Depthwise 3x3 stride-2 pad-1 conv + bias -> g_xs (B,OQ,C)
// ---------------------------------------------------------------------------
__global__ void k_conv(const float* __restrict__ x, const float* __restrict__ w,
                       const float* __restrict__ bias) {
    int bc = blockIdx.x;
    int b = bc >> 9;
    int c = bc & 511;
    __shared__ float sx[HH * HH];
    const float* xp = x + ((size_t)b * CC + c) * NQ;
    for (int i = threadIdx.x; i < HH * HH; i += 256) sx[i] = xp[i];
    float w0 = w[c*9+0], w1 = w[c*9+1], w2 = w[c*9+2];
    float w3 = w[c*9+3], w4 = w[c*9+4], w5 = w[c*9+5];
    float w6 = w[c*9+6], w7 = w[c*9+7], w8 = w[c*9+8];
    float bi = bias[c];
    __syncthreads();
    for (int o = threadIdx.x; o < OQ; o += 256) {
        int oy = o / 28, ox = o - oy * 28;
        int y0 = oy * 2 - 1, x0 = ox * 2 - 1;
        float s = bi;
        if (y0 >= 0) {
            const float* r = &sx[y0 * HH];
            if (x0 >= 0) s += r[x0] * w0;
            s += r[x0 + 1] * w1 + r[x0 + 2] * w2;
        }
        {
            const float* r = &sx[(y0 + 1) * HH];
            if (x0 >= 0) s += r[x0] * w3;
            s += r[x0 + 1] * w4 + r[x0 + 2] * w5;
        }
        {
            const float* r = &sx[(y0 + 2) * HH];
            if (x0 >= 0) s += r[x0] * w6;
            s += r[x0 + 1] * w7 + r[x0 + 2] * w8;
        }
        g_xs[((size_t)b * OQ + o) * CC + c] = s;
    }
}

// ---------------------------------------------------------------------------
// LayerNorm over C=512 per (b,o), in place on g_xs
// ---------------------------------------------------------------------------
__global__ void k_ln(const float* __restrict__ gam, const float* __restrict__ bet) {
    int row = blockIdx.x;
    float* p = g_xs + (size_t)row * CC;
    int tid = threadIdx.x;
    float v0 = p[tid], v1 = p[tid + 256];
    float s = v0 + v1, sq = v0 * v0 + v1 * v1;
    __shared__ float r1[8], r2[8];
    __shared__ float s_m, s_r;
#pragma unroll
    for (int off = 16; off; off >>= 1) {
        s  += __shfl_xor_sync(0xffffffffu, s, off);
        sq += __shfl_xor_sync(0xffffffffu, sq, off);
    }
    if ((tid & 31) == 0) { r1[tid >> 5] = s; r2[tid >> 5] = sq; }
    __syncthreads();
    if (tid == 0) {
        float S = 0.f, Q = 0.f;
        for (int i = 0; i < 8; i++) { S += r1[i]; Q += r2[i]; }
        float mean = S * (1.f / CC);
        float var = Q * (1.f / CC) - mean * mean;
        s_m = mean;
        s_r = rsqrtf(var + LEPS);
    }
    __syncthreads();
    float mean = s_m, rs = s_r;
    p[tid]       = (v0 - mean) * rs * gam[tid]       + bet[tid];
    p[tid + 256] = (v1 - mean) * rs * gam[tid + 256] + bet[tid + 256];
}

// ---------------------------------------------------------------------------
__device__ __forceinline__ float tf32r(float x) {
    uint32_t u;
    asm("cvt.rna.tf32.f32 %0, %1;" : "=r"(u) : "f"(x));
    return __uint_as_float(u);
}
__device__ __forceinline__ float4 tf32r4(float4 v) {
    v.x = tf32r(v.x); v.y = tf32r(v.y); v.z = tf32r(v.z); v.w = tf32r(v.w);
    return v;
}

// ---------------------------------------------------------------------------
// TF32 tensor-core NT GEMM: C[m,n] = alpha * sum_k A[m,k]*W[n,k] (+bias)
// BM=128, BN=64, BK=16; 8 warps (4 M x 2 N), 32x32 warptiles of m16n8k8.
// XOR-swizzled double-buffered smem; ALL smem addresses are precomputed
// per-thread base pointers + compile-time immediates (zero per-access ALU).
// Global loaders use row/col-clamped pointers (garbage discarded in epilogue).
// ---------------------------------------------------------------------------
template <bool TRANS_OUT, bool HAS_BIAS, bool FUSE_A>
__global__ void __launch_bounds__(256)
k_mma(const float* __restrict__ A, int lda, long long sAb, long long sAh,
      const float* __restrict__ W, int ldw, long long sWb, long long sWh,
      float* __restrict__ Cp, int ldc, long long sCb, long long sCh,
      int M, int N, int K, float alpha, const float* __restrict__ bias,
      int trows, const float* __restrict__ A2, const float* __restrict__ rstdp) {
    __shared__ float4 As4[2][4 * BM];   // 512 float4 per buffer
    __shared__ float4 Bs4[2][4 * BN];   // 256 float4 per buffer

    int bz = blockIdx.z;
    long long offA = (long long)(bz >> 3) * sAb + (long long)(bz & 7) * sAh;
    A += offA;
    W += (long long)(bz >> 3) * sWb + (long long)(bz & 7) * sWh;
    Cp += (long long)(bz >> 3) * sCb + (long long)(bz & 7) * sCh;
    float rs = 0.f;
    const float amean = 1.f / OQ;
    if (FUSE_A) { A2 += offA; rs = rstdp[bz]; }

    int m0 = blockIdx.y * BM, n0 = blockIdx.x * BN;
    int tid = threadIdx.x;
    int lane = tid & 31, warp = tid >> 5;
    int wm = (warp & 3) * 32, wn = (warp >> 2) * 32;
    int gid = lane >> 2, tig = lane & 3;
    int lk4 = tid & 3, lrow = tid >> 2;

    // ---- global loader pointers (row/col clamped; results discarded if OOB)
    int gmA0 = min(m0 + lrow, M - 1);
    int gmA1 = min(m0 + lrow + 64, M - 1);
    int gnB  = min(n0 + lrow, N - 1);
    const float* pAg0 = A + (size_t)gmA0 * lda + lk4 * 4;
    const float* pAg1 = A + (size_t)gmA1 * lda + lk4 * 4;
    const float* pWg  = W + (size_t)gnB * ldw + lk4 * 4;
    const float* pA2g0 = nullptr; const float* pA2g1 = nullptr;
    if (FUSE_A) {
        pA2g0 = A2 + (size_t)gmA0 * lda + lk4 * 4;
        pA2g1 = A2 + (size_t)gmA1 * lda + lk4 * 4;
    }

    // ---- smem store pointers (buffer 0); (lrow+64)^c == (lrow^c)+64
    float4* stA = &As4[0][lk4 * BM + (lrow ^ (lk4 << 1))];
    float4* stB = &Bs4[0][lk4 * BN + (lrow ^ (lk4 << 1))];

    // ---- fragment load base pointers (buffer 0); immediates do the rest
    const float* fA[4];
    const float* fB[4];
#pragma unroll
    for (int k4 = 0; k4 < 4; k4++) {
        int gx = gid ^ (k4 << 1);
        fA[k4] = (const float*)As4 + k4 * (BM * 4) + (wm + gx) * 4 + tig;
        fB[k4] = (const float*)Bs4 + k4 * (BN * 4) + (wn + gx) * 4 + tig;
    }

    float acc[2][4][4];
#pragma unroll
    for (int i = 0; i < 2; i++)
#pragma unroll
        for (int j = 0; j < 4; j++)
#pragma unroll
            for (int l = 0; l < 4; l++) acc[i][j][l] = 0.f;

    float4 ra0, ra1, rb;

#define LOAD_TILE()                                                            \
    {                                                                          \
        ra0 = *(const float4*)pAg0;                                            \
        ra1 = *(const float4*)pAg1;                                            \
        rb  = *(const float4*)pWg;                                             \
        if (FUSE_A) {                                                          \
            float4 w0 = *(const float4*)pA2g0;                                 \
            float4 w1 = *(const float4*)pA2g1;                                 \
            ra0.x = (ra0.x - amean) * rs * w0.x;                               \
            ra0.y = (ra0.y - amean) * rs * w0.y;                               \
            ra0.z = (ra0.z - amean) * rs * w0.z;                               \
            ra0.w = (ra0.w - amean) * rs * w0.w;                               \
            ra1.x = (ra1.x - amean) * rs * w1.x;                               \
            ra1.y = (ra1.y - amean) * rs * w1.y;                               \
            ra1.z = (ra1.z - amean) * rs * w1.z;                               \
            ra1.w = (ra1.w - amean) * rs * w1.w;                               \
            pA2g0 += BK; pA2g1 += BK;                                          \
        }                                                                      \
        pAg0 += BK; pAg1 += BK; pWg += BK;                                     \
    }

#define STORE_TILE()                                                           \
    {                                                                          \
        stA[0]  = tf32r4(ra0);                                                 \
        stA[64] = tf32r4(ra1);                                                 \
        stB[0]  = tf32r4(rb);                                                  \
    }

#define COMPUTE()                                                              \
    {                                                                          \
        _Pragma("unroll")                                                      \
        for (int ks = 0; ks < 2; ks++) {                                       \
            const float* a0p = fA[2 * ks];                                     \
            const float* a1p = fA[2 * ks + 1];                                 \
            const float* b0p = fB[2 * ks];                                     \
            const float* b1p = fB[2 * ks + 1];                                 \
            uint32_t af[2][4], bf[4][2];                                       \
            _Pragma("unroll")                                                  \
            for (int mi = 0; mi < 2; mi++) {                                   \
                af[mi][0] = __float_as_uint(a0p[mi * 64]);                     \
                af[mi][1] = __float_as_uint(a0p[mi * 64 + 32]);                \
                af[mi][2] = __float_as_uint(a1p[mi * 64]);                     \
                af[mi][3] = __float_as_uint(a1p[mi * 64 + 32]);                \
            }                                                                  \
            _Pragma("unroll")                                                  \
            for (int ni = 0; ni < 4; ni++) {                                   \
                bf[ni][0] = __float_as_uint(b0p[ni * 32]);                     \
                bf[ni][1] = __float_as_uint(b1p[ni * 32]);                     \
            }                                                                  \
            _Pragma("unroll")                                                  \
            for (int mi = 0; mi < 2; mi++)                                     \
            _Pragma("unroll")                                                  \
            for (int ni = 0; ni < 4; ni++) {                                   \
                asm volatile(                                                  \
                    "mma.sync.aligned.m16n8k8.row.col.f32.tf32.tf32.f32 "      \
                    "{%0,%1,%2,%3}, {%4,%5,%6,%7}, {%8,%9}, {%0,%1,%2,%3};"    \
                    : "+f"(acc[mi][ni][0]), "+f"(acc[mi][ni][1]),              \
                      "+f"(acc[mi][ni][2]), "+f"(acc[mi][ni][3])               \
                    : "r"(af[mi][0]), "r"(af[mi][1]),                          \
                      "r"(af[mi][2]), "r"(af[mi][3]),                          \
                      "r"(bf[ni][0]), "r"(bf[ni][1]));                         \
            }                                                                  \
        }                                                                      \
    }

    LOAD_TILE();
    STORE_TILE();
    __syncthreads();

    int dSA = 512, dSB = 256;      // float4 stride between buffers
    int dFA = 2048, dFB = 1024;    // float stride between buffers
    int nkb = K / BK;
    for (int kb = 0; kb < nkb; kb++) {
        bool more = (kb + 1 < nkb);
        if (more) LOAD_TILE();
        COMPUTE();
        if (more) {
            stA += dSA; stB += dSB; dSA = -dSA; dSB = -dSB;
            STORE_TILE();
#pragma unroll
            for (int k4 = 0; k4 < 4; k4++) { fA[k4] += dFA; fB[k4] += dFB; }
            dFA = -dFA; dFB = -dFB;
            __syncthreads();
        }
    }

    // epilogue
#pragma unroll
    for (int mi = 0; mi < 2; mi++)
#pragma unroll
    for (int ni = 0; ni < 4; ni++) {
        int r0 = m0 + wm + mi * 16 + gid;
        int c0 = n0 + wn + ni * 8 + tig * 2;
#pragma unroll
        for (int half = 0; half < 2; half++) {
            int r = r0 + half * 8;
            if (r >= M) continue;
#pragma unroll
            for (int cc2 = 0; cc2 < 2; cc2++) {
                int c = c0 + cc2;
                if (c >= N) continue;
                float vv = acc[mi][ni][half * 2 + cc2] * alpha;
                if (HAS_BIAS) vv += bias[c];
                if (TRANS_OUT) {
                    int bidx = r / trows, q = r - bidx * trows;
                    Cp[((long long)bidx * N + c) * trows + q] = vv;
                } else {
                    Cp[(long long)r * ldc + c] = vv;
                }
            }
        }
    }
#undef LOAD_TILE
#undef STORE_TILE
#undef COMPUTE
}

// ---------------------------------------------------------------------------
// Fused head-mix (tc_w/tc_b) + softmax over OQ, in place on g_attn.
// All 8 heads reduced concurrently: warp-shfl for 8 quantities -> 8x8 smem
// stage -> warp-group finalize. 5 __syncthreads total. ssq folded into the
// sum pass: pssq = inv^2 * sum(e^2).
// ---------------------------------------------------------------------------
__global__ void __launch_bounds__(256)
k_mixsoftmax(const float* __restrict__ tcw, const float* __restrict__ tcb) {
    int bq = blockIdx.x;
    int b = bq / NQ;
    int q = bq - b * NQ;
    int tid = threadIdx.x;
    int lane = tid & 31, wid = tid >> 5;
    __shared__ float s_w[64];
    __shared__ float s_b[8];
    __shared__ float srA[8][8];
    __shared__ float srB[8][8];
    __shared__ float gmaxs[8];
    __shared__ float ginv[8];
    __shared__ float gssq[8];
    if (tid < 64) s_w[tid] = tcw[tid];
    if (tid < 8)  s_b[tid] = tcb[tid];
    __syncthreads();
    const long long HS = (long long)NQ * OQ;
    long long base0 = (long long)b * NH * HS + (long long)q * OQ;
    float m[8][4];
#pragma unroll
    for (int j = 0; j < 4; j++) {
        int o = tid + j * 256;
        bool valid = o < OQ;
        float lh[8];
#pragma unroll
        for (int h = 0; h < 8; h++)
            lh[h] = valid ? g_attn[base0 + (long long)h * HS + o] : 0.f;
#pragma unroll
        for (int g2 = 0; g2 < 8; g2++) {
            float s = s_b[g2];
#pragma unroll
            for (int h = 0; h < 8; h++) s += s_w[g2 * 8 + h] * lh[h];
            m[g2][j] = valid ? s : -1e30f;
        }
    }
    // phase 1: max for all 8 heads
    float lm[8];
#pragma unroll
    for (int g2 = 0; g2 < 8; g2++)
        lm[g2] = fmaxf(fmaxf(m[g2][0], m[g2][1]), fmaxf(m[g2][2], m[g2][3]));
#pragma unroll
    for (int off = 16; off; off >>= 1)
#pragma unroll
        for (int g2 = 0; g2 < 8; g2++)
            lm[g2] = fmaxf(lm[g2], __shfl_xor_sync(0xffffffffu, lm[g2], off));
    if (lane == 0)
#pragma unroll
        for (int g2 = 0; g2 < 8; g2++) srA[g2][wid] = lm[g2];
    __syncthreads();
    if (tid < 64) {
        float v = srA[tid >> 3][tid & 7];
        v = fmaxf(v, __shfl_xor_sync(0xffffffffu, v, 1));
        v = fmaxf(v, __shfl_xor_sync(0xffffffffu, v, 2));
        v = fmaxf(v, __shfl_xor_sync(0xffffffffu, v, 4));
        if ((tid & 7) == 0) gmaxs[tid >> 3] = v;
    }
    __syncthreads();
    // phase 2: e (overwrites m), sum(e) and sum(e^2)
    float ls[8], l2[8];
#pragma unroll
    for (int g2 = 0; g2 < 8; g2++) {
        float gm_ = gmaxs[g2];
        float a = 0.f, a2 = 0.f;
#pragma unroll
        for (int j = 0; j < 4; j++) {
            float e = __expf(m[g2][j] - gm_);   // invalid lanes: exp(-huge)=0
            m[g2][j] = e;
            a += e; a2 += e * e;
        }
        ls[g2] = a; l2[g2] = a2;
    }
#pragma unroll
    for (int off = 16; off; off >>= 1)
#pragma unroll
        for (int g2 = 0; g2 < 8; g2++) {
            ls[g2] += __shfl_xor_sync(0xffffffffu, ls[g2], off);
            l2[g2] += __shfl_xor_sync(0xffffffffu, l2[g2], off);
        }
    if (lane == 0)
#pragma unroll
        for (int g2 = 0; g2 < 8; g2++) { srA[g2][wid] = ls[g2]; srB[g2][wid] = l2[g2]; }
    __syncthreads();
    if (tid < 64) {
        float v = srA[tid >> 3][tid & 7];
        float v2 = srB[tid >> 3][tid & 7];
        v  += __shfl_xor_sync(0xffffffffu, v, 1);
        v2 += __shfl_xor_sync(0xffffffffu, v2, 1);
        v  += __shfl_xor_sync(0xffffffffu, v, 2);
        v2 += __shfl_xor_sync(0xffffffffu, v2, 2);
        v  += __shfl_xor_sync(0xffffffffu, v, 4);
        v2 += __shfl_xor_sync(0xffffffffu, v2, 4);
        if ((tid & 7) == 0) {
            float inv = 1.f / v;
            ginv[tid >> 3] = inv;
            gssq[tid >> 3] = v2 * inv * inv;
        }
    }
    __syncthreads();
    // write
#pragma unroll
    for (int g2 = 0; g2 < 8; g2++) {
        float inv = ginv[g2];
#pragma unroll
        for (int j = 0; j < 4; j++) {
            int o = tid + j * 256;
            if (o < OQ)
                g_attn[base0 + (long long)g2 * HS + o] = m[g2][j] * inv;
        }
    }
    if (tid < 8)
        g_pssq[(long long)(b * NH + tid) * NQ + q] = gssq[tid];
}

// ---------------------------------------------------------------------------
// Finalize instance-norm rstd per (b,h)
// ---------------------------------------------------------------------------
__global__ void k_rstd() {
    int z = blockIdx.x;
    int tid = threadIdx.x;
    float s = 0.f;
    for (int i = tid; i < NQ; i += 256) s += g_pssq[(long long)z * NQ + i];
    __shared__ float r1[8];
#pragma unroll
    for (int off = 16; off; off >>= 1)
        s += __shfl_xor_sync(0xffffffffu, s, off);
    if ((tid & 31) == 0) r1[tid >> 5] = s;
    __syncthreads();
    if (tid == 0) {
        float S = 0.f;
        for (int i = 0; i < 8; i++) S += r1[i];
        const float mean = 1.f / OQ;
        float var = S / ((float)NQ * (float)OQ) - mean * mean;
        g_rstd[z] = rsqrtf(var + LEPS);
    }
}

// ---------------------------------------------------------------------------
extern "C" void kernel_launch(void* const* d_in, const int* in_sizes, int n_in,
                              void* d_out, int out_size) {
    const float* x    = (const float*)d_in[0];
    const float* aw   = (const float*)d_in[1];
    const float* q_w  = (const float*)d_in[2];
    const float* k_w  = (const float*)d_in[3];
    const float* v_w  = (const float*)d_in[4];
    const float* sr_w = (const float*)d_in[5];
    const float* sr_b = (const float*)d_in[6];
    const float* ln_g = (const float*)d_in[7];
    const float* ln_b = (const float*)d_in[8];
    const float* tc_w = (const float*)d_in[9];
    const float* tc_b = (const float*)d_in[10];
    const float* pj_w = (const float*)d_in[11];
    const float* pj_b = (const float*)d_in[12];
    float* out = (float*)d_out;

    static bool s_init = false;
    static float *p_xf, *p_xs, *p_q, *p_k, *p_vt, *p_attn, *p_ao, *p_rstd;
    if (!s_init) {
        cudaGetSymbolAddress((void**)&p_xf, g_xf);
        cudaGetSymbolAddress((void**)&p_xs, g_xs);
        cudaGetSymbolAddress((void**)&p_q, g_qb);
        cudaGetSymbolAddress((void**)&p_k, g_kb);
        cudaGetSymbolAddress((void**)&p_vt, g_vt);
        cudaGetSymbolAddress((void**)&p_attn, g_attn);
        cudaGetSymbolAddress((void**)&p_ao, g_ao);
        cudaGetSymbolAddress((void**)&p_rstd, g_rstd);
        s_init = true;
    }

    // Stage A: layouts + spatial reduction
    k_transpose<<<dim3(98, 16, 4), dim3(32, 8)>>>(x);
    k_conv<<<BB * CC, 256>>>(x, sr_w, sr_b);
    k_ln<<<BB * OQ, 256>>>(ln_g, ln_b);

    // Stage B: projections (tf32 tensor cores)
    k_mma<false, false, false><<<dim3(8, 98, 1), 256>>>(
        p_xf, CC, 0, 0, q_w, CC, 0, 0, p_q, CC, 0, 0,
        BB * NQ, CC, CC, 1.f, nullptr, 0, nullptr, nullptr);
    k_mma<false, false, false><<<dim3(8, 25, 1), 256>>>(
        p_xs, CC, 0, 0, k_w, CC, 0, 0, p_k, CC, 0, 0,
        BB * OQ, CC, CC, 1.f, nullptr, 0, nullptr, nullptr);
    // V: transposed write -> g_vt (B, C, OQ)
    k_mma<true, false, false><<<dim3(8, 25, 1), 256>>>(
        p_xs, CC, 0, 0, v_w, CC, 0, 0, p_vt, 0, 0, 0,
        BB * OQ, CC, CC, 1.f, nullptr, OQ, nullptr, nullptr);

    // Stage C: per-head QK logits (batched over 32 = B*NH), scaled by hd^-0.5
    k_mma<false, false, false><<<dim3(13, 25, 32), 256>>>(
        p_q, CC, (long long)NQ * CC, HD,
        p_k, CC, (long long)OQ * CC, HD,
        p_attn, OQ, (long long)NH * NQ * OQ, (long long)NQ * OQ,
        NQ, OQ, HD, 0.125f, nullptr, 0, nullptr, nullptr);

    // head-mix + softmax + instnorm stats
    k_mixsoftmax<<<BB * NQ, 256>>>(tc_w, tc_b);
    k_rstd<<<32, 256>>>();

    // Stage D: fused (instnorm * attn_weights) @ V  (V from g_vt, K-contig)
    k_mma<false, false, true><<<dim3(1, 25, 32), 256>>>(
        p_attn, OQ, (long long)NH * NQ * OQ, (long long)NQ * OQ,
        p_vt, OQ, (long long)CC * OQ, (long long)HD * OQ,
        p_ao, CC, (long long)NQ * CC, HD,
        NQ, HD, OQ, 1.f, nullptr, 0, aw, p_rstd);

    // Stage E: output projection + bias, written transposed into (B,C,HW)
    k_mma<true, true, false><<<dim3(8, 98, 1), 256>>>(
        p_ao, CC, 0, 0, pj_w, CC, 0, 0, out, 0, 0, 0,
        BB * NQ, CC, CC, 1.f, pj_b, NQ, nullptr, nullptr);
}

// round 8
// speedup vs baseline: 2.0405x; 1.0635x over previous
#include <cuda_runtime.h>
#include <cstdint>

#define BB 4
#define CC 512
#define HH 56
#define NQ 3136
#define OQ 784
#define NH 8
#define HD 64
#define LEPS 1e-5f

#define BM 128
#define BN 64
#define BK 16

static __device__ float g_xf[(size_t)BB*NQ*CC];
static __device__ float g_xs[(size_t)BB*OQ*CC];
static __device__ float g_qb[(size_t)BB*NQ*CC];
static __device__ float g_kb[(size_t)BB*OQ*CC];
static __device__ float g_vt[(size_t)BB*CC*OQ];    // V transposed: (B, C, OQ)
static __device__ float g_attn[(size_t)BB*NH*NQ*OQ];   // ~315 MB
static __device__ float g_ao[(size_t)BB*NQ*CC];
static __device__ float g_pssq[(size_t)BB*NH*NQ];
static __device__ float g_rstd[BB*NH];

// ---------------------------------------------------------------------------
// Transpose x (B,C,NQ) -> xf (B,NQ,C)
// ---------------------------------------------------------------------------
__global__ void k_transpose(const float* __restrict__ x) {
    __shared__ float t[32][33];
    int b = blockIdx.z;
    int q0 = blockIdx.x * 32, c0 = blockIdx.y * 32;
    int tx = threadIdx.x, ty = threadIdx.y;
#pragma unroll
    for (int i = 0; i < 32; i += 8)
        t[ty + i][tx] = x[((size_t)b * CC + c0 + ty + i) * NQ + q0 + tx];
    __syncthreads();
#pragma unroll
    for (int i = 0; i < 32; i += 8)
        g_xf[((size_t)b * NQ + q0 + ty + i) * CC + c0 + tx] = t[tx][ty + i];
}

// ---------------------------------------------------------------------------
// Depthwise 3x3 stride-2 pad-1 conv + bias -> g_xs (B,OQ,C)
// ---------------------------------------------------------------------------
__global__ void k_conv(const float* __restrict__ x, const float* __restrict__ w,
                       const float* __restrict__ bias) {
    int bc = blockIdx.x;
    int b = bc >> 9;
    int c = bc & 511;
    __shared__ float sx[HH * HH];
    const float* xp = x + ((size_t)b * CC + c) * NQ;
    for (int i = threadIdx.x; i < HH * HH; i += 256) sx[i] = xp[i];
    float w0 = w[c*9+0], w1 = w[c*9+1], w2 = w[c*9+2];
    float w3 = w[c*9+3], w4 = w[c*9+4], w5 = w[c*9+5];
    float w6 = w[c*9+6], w7 = w[c*9+7], w8 = w[c*9+8];
    float bi = bias[c];
    __syncthreads();
    for (int o = threadIdx.x; o < OQ; o += 256) {
        int oy = o / 28, ox = o - oy * 28;
        int y0 = oy * 2 - 1, x0 = ox * 2 - 1;
        float s = bi;
        if (y0 >= 0) {
            const float* r = &sx[y0 * HH];
            if (x0 >= 0) s += r[x0] * w0;
            s += r[x0 + 1] * w1 + r[x0 + 2] * w2;
        }
        {
            const float* r = &sx[(y0 + 1) * HH];
            if (x0 >= 0) s += r[x0] * w3;
            s += r[x0 + 1] * w4 + r[x0 + 2] * w5;
        }
        {
            const float* r = &sx[(y0 + 2) * HH];
            if (x0 >= 0) s += r[x0] * w6;
            s += r[x0 + 1] * w7 + r[x0 + 2] * w8;
        }
        g_xs[((size_t)b * OQ + o) * CC + c] = s;
    }
}

// ---------------------------------------------------------------------------
// LayerNorm over C=512 per (b,o), in place on g_xs
// ---------------------------------------------------------------------------
__global__ void k_ln(const float* __restrict__ gam, const float* __restrict__ bet) {
    int row = blockIdx.x;
    float* p = g_xs + (size_t)row * CC;
    int tid = threadIdx.x;
    float v0 = p[tid], v1 = p[tid + 256];
    float s = v0 + v1, sq = v0 * v0 + v1 * v1;
    __shared__ float r1[8], r2[8];
    __shared__ float s_m, s_r;
#pragma unroll
    for (int off = 16; off; off >>= 1) {
        s  += __shfl_xor_sync(0xffffffffu, s, off);
        sq += __shfl_xor_sync(0xffffffffu, sq, off);
    }
    if ((tid & 31) == 0) { r1[tid >> 5] = s; r2[tid >> 5] = sq; }
    __syncthreads();
    if (tid == 0) {
        float S = 0.f, Q = 0.f;
        for (int i = 0; i < 8; i++) { S += r1[i]; Q += r2[i]; }
        float mean = S * (1.f / CC);
        float var = Q * (1.f / CC) - mean * mean;
        s_m = mean;
        s_r = rsqrtf(var + LEPS);
    }
    __syncthreads();
    float mean = s_m, rs = s_r;
    p[tid]       = (v0 - mean) * rs * gam[tid]       + bet[tid];
    p[tid + 256] = (v1 - mean) * rs * gam[tid + 256] + bet[tid + 256];
}

// ---------------------------------------------------------------------------
__device__ __forceinline__ float tf32r(float x) {
    uint32_t u;
    asm("cvt.rna.tf32.f32 %0, %1;" : "=r"(u) : "f"(x));
    return __uint_as_float(u);
}
__device__ __forceinline__ float4 tf32r4(float4 v) {
    v.x = tf32r(v.x); v.y = tf32r(v.y); v.z = tf32r(v.z); v.w = tf32r(v.w);
    return v;
}

// ---------------------------------------------------------------------------
// TF32 tensor-core NT GEMM: C[m,n] = alpha * sum_k A[m,k]*W[n,k] (+bias)
// BM=128, BN=64, BK=16; 8 warps (4 M x 2 N), 32x32 warptiles of m16n8k8.
// ---------------------------------------------------------------------------
template <bool TRANS_OUT, bool HAS_BIAS, bool FUSE_A>
__global__ void __launch_bounds__(256)
k_mma(const float* __restrict__ A, int lda, long long sAb, long long sAh,
      const float* __restrict__ W, int ldw, long long sWb, long long sWh,
      float* __restrict__ Cp, int ldc, long long sCb, long long sCh,
      int M, int N, int K, float alpha, const float* __restrict__ bias,
      int trows, const float* __restrict__ A2, const float* __restrict__ rstdp) {
    __shared__ float4 As4[2][4 * BM];   // 512 float4 per buffer
    __shared__ float4 Bs4[2][4 * BN];   // 256 float4 per buffer

    int bz = blockIdx.z;
    long long offA = (long long)(bz >> 3) * sAb + (long long)(bz & 7) * sAh;
    A += offA;
    W += (long long)(bz >> 3) * sWb + (long long)(bz & 7) * sWh;
    Cp += (long long)(bz >> 3) * sCb + (long long)(bz & 7) * sCh;
    float rs = 0.f;
    const float amean = 1.f / OQ;
    if (FUSE_A) { A2 += offA; rs = rstdp[bz]; }

    int m0 = blockIdx.y * BM, n0 = blockIdx.x * BN;
    int tid = threadIdx.x;
    int lane = tid & 31, warp = tid >> 5;
    int wm = (warp & 3) * 32, wn = (warp >> 2) * 32;
    int gid = lane >> 2, tig = lane & 3;
    int lk4 = tid & 3, lrow = tid >> 2;

    int gmA0 = min(m0 + lrow, M - 1);
    int gmA1 = min(m0 + lrow + 64, M - 1);
    int gnB  = min(n0 + lrow, N - 1);
    const float* pAg0 = A + (size_t)gmA0 * lda + lk4 * 4;
    const float* pAg1 = A + (size_t)gmA1 * lda + lk4 * 4;
    const float* pWg  = W + (size_t)gnB * ldw + lk4 * 4;
    const float* pA2g0 = nullptr; const float* pA2g1 = nullptr;
    if (FUSE_A) {
        pA2g0 = A2 + (size_t)gmA0 * lda + lk4 * 4;
        pA2g1 = A2 + (size_t)gmA1 * lda + lk4 * 4;
    }

    float4* stA = &As4[0][lk4 * BM + (lrow ^ (lk4 << 1))];
    float4* stB = &Bs4[0][lk4 * BN + (lrow ^ (lk4 << 1))];

    const float* fA[4];
    const float* fB[4];
#pragma unroll
    for (int k4 = 0; k4 < 4; k4++) {
        int gx = gid ^ (k4 << 1);
        fA[k4] = (const float*)As4 + k4 * (BM * 4) + (wm + gx) * 4 + tig;
        fB[k4] = (const float*)Bs4 + k4 * (BN * 4) + (wn + gx) * 4 + tig;
    }

    float acc[2][4][4];
#pragma unroll
    for (int i = 0; i < 2; i++)
#pragma unroll
        for (int j = 0; j < 4; j++)
#pragma unroll
            for (int l = 0; l < 4; l++) acc[i][j][l] = 0.f;

    float4 ra0, ra1, rb;

#define LOAD_TILE()                                                            \
    {                                                                          \
        ra0 = *(const float4*)pAg0;                                            \
        ra1 = *(const float4*)pAg1;                                            \
        rb  = *(const float4*)pWg;                                             \
        if (FUSE_A) {                                                          \
            float4 w0 = *(const float4*)pA2g0;                                 \
            float4 w1 = *(const float4*)pA2g1;                                 \
            ra0.x = (ra0.x - amean) * rs * w0.x;                               \
            ra0.y = (ra0.y - amean) * rs * w0.y;                               \
            ra0.z = (ra0.z - amean) * rs * w0.z;                               \
            ra0.w = (ra0.w - amean) * rs * w0.w;                               \
            ra1.x = (ra1.x - amean) * rs * w1.x;                               \
            ra1.y = (ra1.y - amean) * rs * w1.y;                               \
            ra1.z = (ra1.z - amean) * rs * w1.z;                               \
            ra1.w = (ra1.w - amean) * rs * w1.w;                               \
            pA2g0 += BK; pA2g1 += BK;                                          \
        }                                                                      \
        pAg0 += BK; pAg1 += BK; pWg += BK;                                     \
    }

#define STORE_TILE()                                                           \
    {                                                                          \
        stA[0]  = tf32r4(ra0);                                                 \
        stA[64] = tf32r4(ra1);                                                 \
        stB[0]  = tf32r4(rb);                                                  \
    }

#define COMPUTE()                                                              \
    {                                                                          \
        _Pragma("unroll")                                                      \
        for (int ks = 0; ks < 2; ks++) {                                       \
            const float* a0p = fA[2 * ks];                                     \
            const float* a1p = fA[2 * ks + 1];                                 \
            const float* b0p = fB[2 * ks];                                     \
            const float* b1p = fB[2 * ks + 1];                                 \
            uint32_t af[2][4], bf[4][2];                                       \
            _Pragma("unroll")                                                  \
            for (int mi = 0; mi < 2; mi++) {                                   \
                af[mi][0] = __float_as_uint(a0p[mi * 64]);                     \
                af[mi][1] = __float_as_uint(a0p[mi * 64 + 32]);                \
                af[mi][2] = __float_as_uint(a1p[mi * 64]);                     \
                af[mi][3] = __float_as_uint(a1p[mi * 64 + 32]);                \
            }                                                                  \
            _Pragma("unroll")                                                  \
            for (int ni = 0; ni < 4; ni++) {                                   \
                bf[ni][0] = __float_as_uint(b0p[ni * 32]);                     \
                bf[ni][1] = __float_as_uint(b1p[ni * 32]);                     \
            }                                                                  \
            _Pragma("unroll")                                                  \
            for (int mi = 0; mi < 2; mi++)                                     \
            _Pragma("unroll")                                                  \
            for (int ni = 0; ni < 4; ni++) {                                   \
                asm volatile(                                                  \
                    "mma.sync.aligned.m16n8k8.row.col.f32.tf32.tf32.f32 "      \
                    "{%0,%1,%2,%3}, {%4,%5,%6,%7}, {%8,%9}, {%0,%1,%2,%3};"    \
                    : "+f"(acc[mi][ni][0]), "+f"(acc[mi][ni][1]),              \
                      "+f"(acc[mi][ni][2]), "+f"(acc[mi][ni][3])               \
                    : "r"(af[mi][0]), "r"(af[mi][1]),                          \
                      "r"(af[mi][2]), "r"(af[mi][3]),                          \
                      "r"(bf[ni][0]), "r"(bf[ni][1]));                         \
            }                                                                  \
        }                                                                      \
    }

    LOAD_TILE();
    STORE_TILE();
    __syncthreads();

    int dSA = 512, dSB = 256;
    int dFA = 2048, dFB = 1024;
    int nkb = K / BK;
    for (int kb = 0; kb < nkb; kb++) {
        bool more = (kb + 1 < nkb);
        if (more) LOAD_TILE();
        COMPUTE();
        if (more) {
            stA += dSA; stB += dSB; dSA = -dSA; dSB = -dSB;
            STORE_TILE();
#pragma unroll
            for (int k4 = 0; k4 < 4; k4++) { fA[k4] += dFA; fB[k4] += dFB; }
            dFA = -dFA; dFB = -dFB;
            __syncthreads();
        }
    }

#pragma unroll
    for (int mi = 0; mi < 2; mi++)
#pragma unroll
    for (int ni = 0; ni < 4; ni++) {
        int r0 = m0 + wm + mi * 16 + gid;
        int c0 = n0 + wn + ni * 8 + tig * 2;
#pragma unroll
        for (int half = 0; half < 2; half++) {
            int r = r0 + half * 8;
            if (r >= M) continue;
#pragma unroll
            for (int cc2 = 0; cc2 < 2; cc2++) {
                int c = c0 + cc2;
                if (c >= N) continue;
                float vv = acc[mi][ni][half * 2 + cc2] * alpha;
                if (HAS_BIAS) vv += bias[c];
                if (TRANS_OUT) {
                    int bidx = r / trows, q = r - bidx * trows;
                    Cp[((long long)bidx * N + c) * trows + q] = vv;
                } else {
                    Cp[(long long)r * ldc + c] = vv;
                }
            }
        }
    }
#undef LOAD_TILE
#undef STORE_TILE
#undef COMPUTE
}

// ---------------------------------------------------------------------------
// Specialized QK logits kernel. Block = (b,h, 128 q-rows). Q-tile (128x64,
// full K) resident in smem; stream K-tiles of 64 o-rows (double-buffered via
// registers), full K=64 accumulation per chunk, write 128x64 logits chunk.
// One __syncthreads per chunk. Swizzle: float4 idx k4*ROWS + (row^((k4&3)<<1)).
// ---------------------------------------------------------------------------
#define NCH ((OQ + 63) / 64)   // 13 chunks (last partial: 16 cols)

__global__ void __launch_bounds__(256, 2)
k_qk(const float* __restrict__ Qm, const float* __restrict__ Km,
     float* __restrict__ attn) {
    __shared__ float4 Aq[16 * 128];     // 32 KB
    __shared__ float4 Bk[2][16 * 64];   // 2 x 16 KB

    int z = blockIdx.y;
    int b = z >> 3, h = z & 7;
    int q0 = blockIdx.x * 128;
    const float* Qp = Qm + (size_t)b * NQ * CC + h * HD;
    const float* Kp = Km + (size_t)b * OQ * CC + h * HD;
    float* Op = attn + (size_t)z * NQ * OQ;

    int tid = threadIdx.x;
    int lane = tid & 31, warp = tid >> 5;
    int wm = (warp & 3) * 32, wn = (warp >> 2) * 32;
    int gid = lane >> 2, tig = lane & 3;
    int lk4 = tid & 3, lrow = tid >> 2;      // lrow 0..63

    // ---- load resident A (Q-tile): 4 k-subtiles x 2 row-halves
#pragma unroll
    for (int kt = 0; kt < 4; kt++)
#pragma unroll
        for (int it = 0; it < 2; it++) {
            int r = lrow + it * 64;
            int gm = min(q0 + r, NQ - 1);
            float4 v = *(const float4*)(Qp + (size_t)gm * CC + kt * 16 + lk4 * 4);
            Aq[(kt * 4 + lk4) * 128 + (r ^ (lk4 << 1))] = tf32r4(v);
        }

    // ---- B chunk loader (64 o-rows x 64 k): 4 k-subtiles, 1 row pass
    float4 rbv[4];
#define LOADB(J)                                                               \
    {                                                                          \
        int go = min((J) * 64 + lrow, OQ - 1);                                 \
        const float* src = Kp + (size_t)go * CC + lk4 * 4;                     \
        _Pragma("unroll")                                                      \
        for (int kt = 0; kt < 4; kt++) rbv[kt] = *(const float4*)(src + kt * 16); \
    }
#define STOREB(BUF)                                                            \
    {                                                                          \
        _Pragma("unroll")                                                      \
        for (int kt = 0; kt < 4; kt++)                                         \
            Bk[BUF][(kt * 4 + lk4) * 64 + (lrow ^ (lk4 << 1))] = tf32r4(rbv[kt]); \
    }

    LOADB(0);
    STOREB(0);
    __syncthreads();

    const float* Af = (const float*)Aq;
    for (int j = 0; j < NCH; j++) {
        int buf = j & 1;
        bool more = (j + 1 < NCH);
        if (more) LOADB(j + 1);

        float acc[2][4][4];
#pragma unroll
        for (int i = 0; i < 2; i++)
#pragma unroll
            for (int jj = 0; jj < 4; jj++)
#pragma unroll
                for (int l = 0; l < 4; l++) acc[i][jj][l] = 0.f;

        const float* Bf = (const float*)Bk[buf];
#pragma unroll
        for (int ks = 0; ks < 8; ks++) {
            const int k4a = 2 * ks, k4b = 2 * ks + 1;
            const int ca = (k4a & 3) << 1, cb = (k4b & 3) << 1;
            uint32_t af[2][4], bf[4][2];
#pragma unroll
            for (int mi = 0; mi < 2; mi++) {
                int ra = (wm + mi * 16 + gid) ^ ca;
                int rb2 = (wm + mi * 16 + gid) ^ cb;
                af[mi][0] = __float_as_uint(Af[(k4a * 128 + ra) * 4 + tig]);
                af[mi][1] = __float_as_uint(Af[(k4a * 128 + ra + 8) * 4 + tig]);
                af[mi][2] = __float_as_uint(Af[(k4b * 128 + rb2) * 4 + tig]);
                af[mi][3] = __float_as_uint(Af[(k4b * 128 + rb2 + 8) * 4 + tig]);
            }
#pragma unroll
            for (int ni = 0; ni < 4; ni++) {
                int na = (wn + ni * 8 + gid) ^ ca;
                int nb = (wn + ni * 8 + gid) ^ cb;
                bf[ni][0] = __float_as_uint(Bf[(k4a * 64 + na) * 4 + tig]);
                bf[ni][1] = __float_as_uint(Bf[(k4b * 64 + nb) * 4 + tig]);
            }
#pragma unroll
            for (int mi = 0; mi < 2; mi++)
#pragma unroll
            for (int ni = 0; ni < 4; ni++) {
                asm volatile(
                    "mma.sync.aligned.m16n8k8.row.col.f32.tf32.tf32.f32 "
                    "{%0,%1,%2,%3}, {%4,%5,%6,%7}, {%8,%9}, {%0,%1,%2,%3};"
                    : "+f"(acc[mi][ni][0]), "+f"(acc[mi][ni][1]),
                      "+f"(acc[mi][ni][2]), "+f"(acc[mi][ni][3])
                    : "r"(af[mi][0]), "r"(af[mi][1]),
                      "r"(af[mi][2]), "r"(af[mi][3]),
                      "r"(bf[ni][0]), "r"(bf[ni][1]));
            }
        }

        // epilogue: write logits chunk, scaled
        int o0 = j * 64;
#pragma unroll
        for (int mi = 0; mi < 2; mi++)
#pragma unroll
        for (int ni = 0; ni < 4; ni++) {
            int r0 = q0 + wm + mi * 16 + gid;
            int c0 = o0 + wn + ni * 8 + tig * 2;
#pragma unroll
            for (int half = 0; half < 2; half++) {
                int r = r0 + half * 8;
                if (r >= NQ) continue;
#pragma unroll
                for (int cc2 = 0; cc2 < 2; cc2++) {
                    int c = c0 + cc2;
                    if (c >= OQ) continue;
                    Op[(size_t)r * OQ + c] = acc[mi][ni][half * 2 + cc2] * 0.125f;
                }
            }
        }

        if (more) {
            STOREB(buf ^ 1);
            __syncthreads();
        }
    }
#undef LOADB
#undef STOREB
}

// ---------------------------------------------------------------------------
// Fused head-mix (tc_w/tc_b) + softmax over OQ, in place on g_attn.
// ---------------------------------------------------------------------------
__global__ void __launch_bounds__(256)
k_mixsoftmax(const float* __restrict__ tcw, const float* __restrict__ tcb) {
    int bq = blockIdx.x;
    int b = bq / NQ;
    int q = bq - b * NQ;
    int tid = threadIdx.x;
    int lane = tid & 31, wid = tid >> 5;
    __shared__ float s_w[64];
    __shared__ float s_b[8];
    __shared__ float srA[8][8];
    __shared__ float srB[8][8];
    __shared__ float gmaxs[8];
    __shared__ float ginv[8];
    __shared__ float gssq[8];
    if (tid < 64) s_w[tid] = tcw[tid];
    if (tid < 8)  s_b[tid] = tcb[tid];
    __syncthreads();
    const long long HS = (long long)NQ * OQ;
    long long base0 = (long long)b * NH * HS + (long long)q * OQ;
    float m[8][4];
#pragma unroll
    for (int j = 0; j < 4; j++) {
        int o = tid + j * 256;
        bool valid = o < OQ;
        float lh[8];
#pragma unroll
        for (int h = 0; h < 8; h++)
            lh[h] = valid ? g_attn[base0 + (long long)h * HS + o] : 0.f;
#pragma unroll
        for (int g2 = 0; g2 < 8; g2++) {
            float s = s_b[g2];
#pragma unroll
            for (int h = 0; h < 8; h++) s += s_w[g2 * 8 + h] * lh[h];
            m[g2][j] = valid ? s : -1e30f;
        }
    }
    float lm[8];
#pragma unroll
    for (int g2 = 0; g2 < 8; g2++)
        lm[g2] = fmaxf(fmaxf(m[g2][0], m[g2][1]), fmaxf(m[g2][2], m[g2][3]));
#pragma unroll
    for (int off = 16; off; off >>= 1)
#pragma unroll
        for (int g2 = 0; g2 < 8; g2++)
            lm[g2] = fmaxf(lm[g2], __shfl_xor_sync(0xffffffffu, lm[g2], off));
    if (lane == 0)
#pragma unroll
        for (int g2 = 0; g2 < 8; g2++) srA[g2][wid] = lm[g2];
    __syncthreads();
    if (tid < 64) {
        float v = srA[tid >> 3][tid & 7];
        v = fmaxf(v, __shfl_xor_sync(0xffffffffu, v, 1));
        v = fmaxf(v, __shfl_xor_sync(0xffffffffu, v, 2));
        v = fmaxf(v, __shfl_xor_sync(0xffffffffu, v, 4));
        if ((tid & 7) == 0) gmaxs[tid >> 3] = v;
    }
    __syncthreads();
    float ls[8], l2[8];
#pragma unroll
    for (int g2 = 0; g2 < 8; g2++) {
        float gm_ = gmaxs[g2];
        float a = 0.f, a2 = 0.f;
#pragma unroll
        for (int j = 0; j < 4; j++) {
            float e = __expf(m[g2][j] - gm_);
            m[g2][j] = e;
            a += e; a2 += e * e;
        }
        ls[g2] = a; l2[g2] = a2;
    }
#pragma unroll
    for (int off = 16; off; off >>= 1)
#pragma unroll
        for (int g2 = 0; g2 < 8; g2++) {
            ls[g2] += __shfl_xor_sync(0xffffffffu, ls[g2], off);
            l2[g2] += __shfl_xor_sync(0xffffffffu, l2[g2], off);
        }
    if (lane == 0)
#pragma unroll
        for (int g2 = 0; g2 < 8; g2++) { srA[g2][wid] = ls[g2]; srB[g2][wid] = l2[g2]; }
    __syncthreads();
    if (tid < 64) {
        float v = srA[tid >> 3][tid & 7];
        float v2 = srB[tid >> 3][tid & 7];
        v  += __shfl_xor_sync(0xffffffffu, v, 1);
        v2 += __shfl_xor_sync(0xffffffffu, v2, 1);
        v  += __shfl_xor_sync(0xffffffffu, v, 2);
        v2 += __shfl_xor_sync(0xffffffffu, v2, 2);
        v  += __shfl_xor_sync(0xffffffffu, v, 4);
        v2 += __shfl_xor_sync(0xffffffffu, v2, 4);
        if ((tid & 7) == 0) {
            float inv = 1.f / v;
            ginv[tid >> 3] = inv;
            gssq[tid >> 3] = v2 * inv * inv;
        }
    }
    __syncthreads();
#pragma unroll
    for (int g2 = 0; g2 < 8; g2++) {
        float inv = ginv[g2];
#pragma unroll
        for (int j = 0; j < 4; j++) {
            int o = tid + j * 256;
            if (o < OQ)
                g_attn[base0 + (long long)g2 * HS + o] = m[g2][j] * inv;
        }
    }
    if (tid < 8)
        g_pssq[(long long)(b * NH + tid) * NQ + q] = gssq[tid];
}

// ---------------------------------------------------------------------------
// Finalize instance-norm rstd per (b,h)
// ---------------------------------------------------------------------------
__global__ void k_rstd() {
    int z = blockIdx.x;
    int tid = threadIdx.x;
    float s = 0.f;
    for (int i = tid; i < NQ; i += 256) s += g_pssq[(long long)z * NQ + i];
    __shared__ float r1[8];
#pragma unroll
    for (int off = 16; off; off >>= 1)
        s += __shfl_xor_sync(0xffffffffu, s, off);
    if ((tid & 31) == 0) r1[tid >> 5] = s;
    __syncthreads();
    if (tid == 0) {
        float S = 0.f;
        for (int i = 0; i < 8; i++) S += r1[i];
        const float mean = 1.f / OQ;
        float var = S / ((float)NQ * (float)OQ) - mean * mean;
        g_rstd[z] = rsqrtf(var + LEPS);
    }
}

// ---------------------------------------------------------------------------
extern "C" void kernel_launch(void* const* d_in, const int* in_sizes, int n_in,
                              void* d_out, int out_size) {
    const float* x    = (const float*)d_in[0];
    const float* aw   = (const float*)d_in[1];
    const float* q_w  = (const float*)d_in[2];
    const float* k_w  = (const float*)d_in[3];
    const float* v_w  = (const float*)d_in[4];
    const float* sr_w = (const float*)d_in[5];
    const float* sr_b = (const float*)d_in[6];
    const float* ln_g = (const float*)d_in[7];
    const float* ln_b = (const float*)d_in[8];
    const float* tc_w = (const float*)d_in[9];
    const float* tc_b = (const float*)d_in[10];
    const float* pj_w = (const float*)d_in[11];
    const float* pj_b = (const float*)d_in[12];
    float* out = (float*)d_out;

    static bool s_init = false;
    static float *p_xf, *p_xs, *p_q, *p_k, *p_vt, *p_attn, *p_ao, *p_rstd;
    if (!s_init) {
        cudaGetSymbolAddress((void**)&p_xf, g_xf);
        cudaGetSymbolAddress((void**)&p_xs, g_xs);
        cudaGetSymbolAddress((void**)&p_q, g_qb);
        cudaGetSymbolAddress((void**)&p_k, g_kb);
        cudaGetSymbolAddress((void**)&p_vt, g_vt);
        cudaGetSymbolAddress((void**)&p_attn, g_attn);
        cudaGetSymbolAddress((void**)&p_ao, g_ao);
        cudaGetSymbolAddress((void**)&p_rstd, g_rstd);
        s_init = true;
    }

    // Stage A: layouts + spatial reduction
    k_transpose<<<dim3(98, 16, 4), dim3(32, 8)>>>(x);
    k_conv<<<BB * CC, 256>>>(x, sr_w, sr_b);
    k_ln<<<BB * OQ, 256>>>(ln_g, ln_b);

    // Stage B: projections (tf32 tensor cores)
    k_mma<false, false, false><<<dim3(8, 98, 1), 256>>>(
        p_xf, CC, 0, 0, q_w, CC, 0, 0, p_q, CC, 0, 0,
        BB * NQ, CC, CC, 1.f, nullptr, 0, nullptr, nullptr);
    k_mma<false, false, false><<<dim3(8, 25, 1), 256>>>(
        p_xs, CC, 0, 0, k_w, CC, 0, 0, p_k, CC, 0, 0,
        BB * OQ, CC, CC, 1.f, nullptr, 0, nullptr, nullptr);
    // V: transposed write -> g_vt (B, C, OQ)
    k_mma<true, false, false><<<dim3(8, 25, 1), 256>>>(
        p_xs, CC, 0, 0, v_w, CC, 0, 0, p_vt, 0, 0, 0,
        BB * OQ, CC, CC, 1.f, nullptr, OQ, nullptr, nullptr);

    // Stage C: specialized Q-resident QK logits kernel
    k_qk<<<dim3(25, 32), 256>>>(p_q, p_k, p_attn);

    // head-mix + softmax + instnorm stats
    k_mixsoftmax<<<BB * NQ, 256>>>(tc_w, tc_b);
    k_rstd<<<32, 256>>>();

    // Stage D: fused (instnorm * attn_weights) @ V  (V from g_vt, K-contig)
    k_mma<false, false, true><<<dim3(1, 25, 32), 256>>>(
        p_attn, OQ, (long long)NH * NQ * OQ, (long long)NQ * OQ,
        p_vt, OQ, (long long)CC * OQ, (long long)HD * OQ,
        p_ao, CC, (long long)NQ * CC, HD,
        NQ, HD, OQ, 1.f, nullptr, 0, aw, p_rstd);

    // Stage E: output projection + bias, written transposed into (B,C,HW)
    k_mma<true, true, false><<<dim3(8, 98, 1), 256>>>(
        p_ao, CC, 0, 0, pj_w, CC, 0, 0, out, 0, 0, 0,
        BB * NQ, CC, CC, 1.f, pj_b, NQ, nullptr, nullptr);
}